// round 4
// baseline (speedup 1.0000x reference)
#include <cuda_runtime.h>

// image [B=4, C=1, D=128, H=256, W=256] fp32
// out   [B, 2, D, H, W]: ch0 = copy, ch1 = sqrt(Gx^2+Gy^2+Gz^2 + 1e-8)
#define DIM_D 128
#define DIM_H 256
#define DIM_W 256
#define PLANE (DIM_H * DIM_W)
#define DCHUNK 32
#define W4 64   // float4 columns per row

__global__ void __launch_bounds__(256)
sobel_edge_kernel(const float* __restrict__ img, float* __restrict__ out)
{
    // Double-buffered w-partials for 6 input rows (4 output rows + halo):
    //   sU = s_w(x) (smooth along w), sV = d_w(x) (derivative along w)
    __shared__ float4 sU[2][6][W4];
    __shared__ float4 sV[2][6][W4];

    const int tx = threadIdx.x;       // 0..63 -> w (float4 each)
    const int ty = threadIdx.y;       // 0..3  -> output h row
    const int w0 = tx * 4;
    const int h0 = blockIdx.y * 4;    // first output row of this block
    const int h  = h0 + ty;
    const int d0 = blockIdx.x * DCHUNK;
    const int b  = blockIdx.z;

    const float* base = img + (size_t)b * (DIM_D * PLANE);
    float* o0 = out + (size_t)b * 2 * (DIM_D * PLANE) + (size_t)h * DIM_W + w0;
    float* o1 = o0 + (size_t)(DIM_D * PLANE);

    // Stage plane p's w-partials into smem buffer s.
    // 6 input rows (h0-1 .. h0+4): rows 0..3 by ty 0..3, rows 4,5 by ty 0,1.
    auto stage = [&](int p, bool pv, int s) {
#pragma unroll
        for (int i = 0; i < 2; i++) {
            if (i == 1 && ty >= 2) break;
            const int r = ty + i * 4;          // 0..5
            const int g = h0 - 1 + r;          // global input row
            float4 c = make_float4(0.f, 0.f, 0.f, 0.f);
            float xl = 0.f, xr = 0.f;
            if (pv && g >= 0 && g < DIM_H) {
                const float* row = base + (size_t)p * PLANE + (size_t)g * DIM_W + w0;
                c = __ldg(reinterpret_cast<const float4*>(row));
                if (w0 > 0)          xl = __ldg(row - 1);
                if (w0 + 4 < DIM_W)  xr = __ldg(row + 4);
            }
            float4 u, v;
            u.x = xl  + 2.f * c.x + c.y;
            u.y = c.x + 2.f * c.y + c.z;
            u.z = c.y + 2.f * c.z + c.w;
            u.w = c.z + 2.f * c.w + xr;
            v.x = c.y - xl;
            v.y = c.z - c.x;
            v.z = c.w - c.y;
            v.w = xr  - c.z;
            sU[s][r][tx] = u;
            sV[s][r][tx] = v;
        }
    };

    // h-combine from smem buffer s at this thread's output row:
    //   A = s_h(u) (Gz=d_d(A)); B = s_h(v) (Gx=s_d(B)); C = d_h(u) (Gy=s_d(C))
    auto combine = [&](int s, float4& A, float4& B, float4& C) {
        const float4 u0 = sU[s][ty][tx], u1 = sU[s][ty + 1][tx], u2 = sU[s][ty + 2][tx];
        const float4 v0 = sV[s][ty][tx], v1 = sV[s][ty + 1][tx], v2 = sV[s][ty + 2][tx];
        A.x = u0.x + 2.f * u1.x + u2.x;
        A.y = u0.y + 2.f * u1.y + u2.y;
        A.z = u0.z + 2.f * u1.z + u2.z;
        A.w = u0.w + 2.f * u1.w + u2.w;
        B.x = v0.x + 2.f * v1.x + v2.x;
        B.y = v0.y + 2.f * v1.y + v2.y;
        B.z = v0.z + 2.f * v1.z + v2.z;
        B.w = v0.w + 2.f * v1.w + v2.w;
        C.x = u2.x - u0.x;
        C.y = u2.y - u0.y;
        C.z = u2.z - u0.z;
        C.w = u2.w - u0.w;
    };

    // Raw center value at this thread's output row (copy channel); guaranteed
    // L1 hit: a block-mate loads the same line for staging.
    auto load_cen = [&](int p, bool pv) -> float4 {
        if (!pv) return make_float4(0.f, 0.f, 0.f, 0.f);
        return __ldg(reinterpret_cast<const float4*>(
            base + (size_t)p * PLANE + (size_t)h * DIM_W + w0));
    };

    float4 A0, B0, C0, A1, B1, C1, A2, B2, C2, cen1, cen2, cenN;

    // Prologue: plane d0-1 -> stage 0, plane d0 -> stage 1
    stage(d0 - 1, (d0 - 1) >= 0, 0);
    stage(d0, true, 1);
    cen2 = load_cen(d0, true);
    __syncthreads();
    combine(0, A1, B1, C1);
    combine(1, A2, B2, C2);
    __syncthreads();   // prologue reads done before loop's first write to stage 0

#pragma unroll 2
    for (int dd = 0; dd <= DCHUNK; dd++) {
        const int p = d0 + dd + 1;
        const bool lv = (dd < DCHUNK) && (p < DIM_D);
        const int s = dd & 1;

        // (1) stage next plane's w-partials (STS) + prefetch its center row
        stage(p, lv, s);
        cenN = load_cen(p, lv);

        // (2) compute + store output plane d0+dd-1 from the register ring
        if (dd >= 1) {
            const int d = d0 + dd - 1;
            float4 gx, gy, gz, m;
            gx.x = B0.x + 2.f * B1.x + B2.x;
            gx.y = B0.y + 2.f * B1.y + B2.y;
            gx.z = B0.z + 2.f * B1.z + B2.z;
            gx.w = B0.w + 2.f * B1.w + B2.w;
            gy.x = C0.x + 2.f * C1.x + C2.x;
            gy.y = C0.y + 2.f * C1.y + C2.y;
            gy.z = C0.z + 2.f * C1.z + C2.z;
            gy.w = C0.w + 2.f * C1.w + C2.w;
            gz.x = A2.x - A0.x;
            gz.y = A2.y - A0.y;
            gz.z = A2.z - A0.z;
            gz.w = A2.w - A0.w;
            m.x = sqrtf(fmaf(gx.x, gx.x, fmaf(gy.x, gy.x, fmaf(gz.x, gz.x, 1e-8f))));
            m.y = sqrtf(fmaf(gx.y, gx.y, fmaf(gy.y, gy.y, fmaf(gz.y, gz.y, 1e-8f))));
            m.z = sqrtf(fmaf(gx.z, gx.z, fmaf(gy.z, gy.z, fmaf(gz.z, gz.z, 1e-8f))));
            m.w = sqrtf(fmaf(gx.w, gx.w, fmaf(gy.w, gy.w, fmaf(gz.w, gz.w, 1e-8f))));

            const size_t off = (size_t)d * PLANE;
            __stcs(reinterpret_cast<float4*>(o0 + off), cen1);  // copy channel
            __stcs(reinterpret_cast<float4*>(o1 + off), m);     // magnitude channel
        }

        // (3) barrier, then fold the just-staged plane into the ring
        __syncthreads();
        if (dd < DCHUNK) {
            A0 = A1; B0 = B1; C0 = C1;
            A1 = A2; B1 = B2; C1 = C2;
            cen1 = cen2; cen2 = cenN;
            combine(s, A2, B2, C2);
        }
    }
}

extern "C" void kernel_launch(void* const* d_in, const int* in_sizes, int n_in,
                              void* d_out, int out_size)
{
    const float* img = (const float*)d_in[0];
    float* out = (float*)d_out;

    dim3 block(64, 4, 1);                       // 256 threads
    dim3 grid(DIM_D / DCHUNK, DIM_H / 4, 4);    // 4 x 64 x 4 = 1024 CTAs

    sobel_edge_kernel<<<grid, block>>>(img, out);
}

// round 5
// speedup vs baseline: 1.5353x; 1.5353x over previous
#include <cuda_runtime.h>

// image [B=4, C=1, D=128, H=256, W=256] fp32
// out   [B, 2, D, H, W]: ch0 = copy, ch1 = sqrt(Gx^2+Gy^2+Gz^2 + 1e-8)
#define DIM_D 128
#define DIM_H 256
#define DIM_W 256
#define PLANE (DIM_H * DIM_W)
#define DCHUNK 64

struct Raw {
    float4 c0, c1, c2;       // rows h-1, h, h+1 (float4 at w0)
    float  l0, l1, l2;       // w-left halo scalars
    float  r0, r1, r2;       // w-right halo scalars
};

// Issue all 9 loads for one plane via immediate offsets off a single pointer.
__device__ __forceinline__ void load_raw(
    const float* __restrict__ rp,   // points at (plane, h, w0)
    bool pv, bool v0, bool v2, bool wl, bool wr, Raw& q)
{
    q.c0 = make_float4(0.f, 0.f, 0.f, 0.f);
    q.c1 = q.c0; q.c2 = q.c0;
    q.l0 = q.l1 = q.l2 = 0.f;
    q.r0 = q.r1 = q.r2 = 0.f;
    if (pv) {
        if (v0) {
            q.c0 = __ldg(reinterpret_cast<const float4*>(rp - DIM_W));
            if (wl) q.l0 = __ldg(rp - DIM_W - 1);
            if (wr) q.r0 = __ldg(rp - DIM_W + 4);
        }
        q.c1 = __ldg(reinterpret_cast<const float4*>(rp));
        if (wl) q.l1 = __ldg(rp - 1);
        if (wr) q.r1 = __ldg(rp + 4);
        if (v2) {
            q.c2 = __ldg(reinterpret_cast<const float4*>(rp + DIM_W));
            if (wl) q.l2 = __ldg(rp + DIM_W - 1);
            if (wr) q.r2 = __ldg(rp + DIM_W + 4);
        }
    }
}

// Fold raw plane into separable partials:
//   A = s_h*s_w(x) (Gz=d_d(A)); B = s_h*d_w(x) (Gx=s_d(B)); C = d_h*s_w(x) (Gy=s_d(C))
__device__ __forceinline__ void fold(
    const Raw& q, float4& A, float4& B, float4& C, float4& cen)
{
    float4 u0, u1, u2, v0, v1, v2;
    u0.x = q.l0   + 2.f * q.c0.x + q.c0.y;
    u0.y = q.c0.x + 2.f * q.c0.y + q.c0.z;
    u0.z = q.c0.y + 2.f * q.c0.z + q.c0.w;
    u0.w = q.c0.z + 2.f * q.c0.w + q.r0;
    v0.x = q.c0.y - q.l0;
    v0.y = q.c0.z - q.c0.x;
    v0.z = q.c0.w - q.c0.y;
    v0.w = q.r0   - q.c0.z;

    u1.x = q.l1   + 2.f * q.c1.x + q.c1.y;
    u1.y = q.c1.x + 2.f * q.c1.y + q.c1.z;
    u1.z = q.c1.y + 2.f * q.c1.z + q.c1.w;
    u1.w = q.c1.z + 2.f * q.c1.w + q.r1;
    v1.x = q.c1.y - q.l1;
    v1.y = q.c1.z - q.c1.x;
    v1.z = q.c1.w - q.c1.y;
    v1.w = q.r1   - q.c1.z;

    u2.x = q.l2   + 2.f * q.c2.x + q.c2.y;
    u2.y = q.c2.x + 2.f * q.c2.y + q.c2.z;
    u2.z = q.c2.y + 2.f * q.c2.z + q.c2.w;
    u2.w = q.c2.z + 2.f * q.c2.w + q.r2;
    v2.x = q.c2.y - q.l2;
    v2.y = q.c2.z - q.c2.x;
    v2.z = q.c2.w - q.c2.y;
    v2.w = q.r2   - q.c2.z;

    cen = q.c1;
    A.x = u0.x + 2.f * u1.x + u2.x;
    A.y = u0.y + 2.f * u1.y + u2.y;
    A.z = u0.z + 2.f * u1.z + u2.z;
    A.w = u0.w + 2.f * u1.w + u2.w;
    B.x = v0.x + 2.f * v1.x + v2.x;
    B.y = v0.y + 2.f * v1.y + v2.y;
    B.z = v0.z + 2.f * v1.z + v2.z;
    B.w = v0.w + 2.f * v1.w + v2.w;
    C.x = u2.x - u0.x;
    C.y = u2.y - u0.y;
    C.z = u2.z - u0.z;
    C.w = u2.w - u0.w;
}

__global__ void __launch_bounds__(128)
sobel_edge_kernel(const float* __restrict__ img, float* __restrict__ out)
{
    const int tx = threadIdx.x;            // 0..63 -> w (float4)
    const int ty = threadIdx.y;            // 0..1  -> h row
    const int w0 = tx * 4;
    const int h  = blockIdx.x * 2 + ty;    // h fastest: adjacent CTAs share halo rows in L2
    const int d0 = blockIdx.y * DCHUNK;
    const int b  = blockIdx.z;

    const bool v0 = h > 0, v2 = h < DIM_H - 1;
    const bool wl = w0 > 0, wr = (w0 + 4) < DIM_W;

    // Single input row pointer, starts at plane d0-1 (address formed but not
    // dereferenced when invalid); advanced by PLANE per plane.
    const float* rp = img + (size_t)b * (DIM_D * PLANE)
                    + (size_t)(d0 - 1) * PLANE + (size_t)h * DIM_W + w0;

    // Output pointers start at plane d0; advanced by PLANE per store.
    float* o0 = out + (size_t)b * 2 * (DIM_D * PLANE)
              + (size_t)d0 * PLANE + (size_t)h * DIM_W + w0;
    float* o1 = o0 + (size_t)(DIM_D * PLANE);

    float4 A0, B0, C0, A1, B1, C1, A2, B2, C2, cen1, cen2, dummy;
    Raw q;

    // Prologue: plane d0-1 -> slot1, plane d0 -> slot2
    load_raw(rp, d0 > 0, v0, v2, wl, wr, q);
    fold(q, A1, B1, C1, dummy);
    rp += PLANE;
    load_raw(rp, true, v0, v2, wl, wr, q);
    fold(q, A2, B2, C2, cen2);
    rp += PLANE;

#pragma unroll 3
    for (int dd = 0; dd <= DCHUNK; dd++) {
        // (1) issue next-plane loads (plane d0+dd+1), consumed at step (3)
        const bool lv = (dd < DCHUNK) && (d0 + dd + 1 < DIM_D);
        load_raw(rp, lv, v0, v2, wl, wr, q);
        rp += PLANE;

        // (2) compute + store output plane d0+dd-1 from the register ring
        if (dd >= 1) {
            float4 gx, gy, gz, m;
            gx.x = B0.x + 2.f * B1.x + B2.x;
            gx.y = B0.y + 2.f * B1.y + B2.y;
            gx.z = B0.z + 2.f * B1.z + B2.z;
            gx.w = B0.w + 2.f * B1.w + B2.w;
            gy.x = C0.x + 2.f * C1.x + C2.x;
            gy.y = C0.y + 2.f * C1.y + C2.y;
            gy.z = C0.z + 2.f * C1.z + C2.z;
            gy.w = C0.w + 2.f * C1.w + C2.w;
            gz.x = A2.x - A0.x;
            gz.y = A2.y - A0.y;
            gz.z = A2.z - A0.z;
            gz.w = A2.w - A0.w;
            m.x = sqrtf(fmaf(gx.x, gx.x, fmaf(gy.x, gy.x, fmaf(gz.x, gz.x, 1e-8f))));
            m.y = sqrtf(fmaf(gx.y, gx.y, fmaf(gy.y, gy.y, fmaf(gz.y, gz.y, 1e-8f))));
            m.z = sqrtf(fmaf(gx.z, gx.z, fmaf(gy.z, gy.z, fmaf(gz.z, gz.z, 1e-8f))));
            m.w = sqrtf(fmaf(gx.w, gx.w, fmaf(gy.w, gy.w, fmaf(gz.w, gz.w, 1e-8f))));

            __stcs(reinterpret_cast<float4*>(o0), cen1);  // copy channel
            __stcs(reinterpret_cast<float4*>(o1), m);     // magnitude channel
            o0 += PLANE;
            o1 += PLANE;
        }

        // (3) rotate ring; fold the just-loaded plane into slot 2
        if (dd < DCHUNK) {
            A0 = A1; B0 = B1; C0 = C1;
            A1 = A2; B1 = B2; C1 = C2;
            cen1 = cen2;
            fold(q, A2, B2, C2, cen2);
        }
    }
}

extern "C" void kernel_launch(void* const* d_in, const int* in_sizes, int n_in,
                              void* d_out, int out_size)
{
    const float* img = (const float*)d_in[0];
    float* out = (float*)d_out;

    dim3 block(64, 2, 1);                        // 128 threads
    dim3 grid(DIM_H / 2, DIM_D / DCHUNK, 4);     // 128 x 2 x 4 = 1024 CTAs

    sobel_edge_kernel<<<grid, block>>>(img, out);
}

// round 6
// speedup vs baseline: 1.6304x; 1.0619x over previous
#include <cuda_runtime.h>

// image [B=4, C=1, D=128, H=256, W=256] fp32
// out   [B, 2, D, H, W]: ch0 = copy, ch1 = sqrt(Gx^2+Gy^2+Gz^2 + 1e-8)
#define DIM_D 128
#define DIM_H 256
#define DIM_W 256
#define PLANE (DIM_H * DIM_W)
#define DCHUNK 32

// Load one plane (3 rows + w-halos), fold to separable partials, and
// optionally store the copy channel for this plane immediately (kills the
// cen register ring). Accumulates row-by-row to minimize live temps.
//   A = s_h*s_w(x) (Gz=d_d(A)); B = s_h*d_w(x) (Gx=s_d(B)); C = d_h*s_w(x) (Gy=s_d(C))
__device__ __forceinline__ void load_fold(
    const float* __restrict__ rp,   // (plane, h, w0)
    float* __restrict__ copy_dst,   // out ch0 (plane, h, w0) or nullptr
    bool pv, bool v0, bool v2, bool wl, bool wr,
    float4& A, float4& B, float4& C)
{
    A = make_float4(0.f, 0.f, 0.f, 0.f);
    B = A; C = A;
    if (!pv) return;

#pragma unroll
    for (int r = 0; r < 3; r++) {
        const bool rv = (r == 0) ? v0 : (r == 2 ? v2 : true);
        if (!rv) continue;
        const float* row = rp + (r - 1) * DIM_W;
        const float4 c = __ldg(reinterpret_cast<const float4*>(row));
        const float xl = wl ? __ldg(row - 1) : 0.f;
        const float xr = wr ? __ldg(row + 4) : 0.f;

        if (r == 1 && copy_dst) {
            __stcs(reinterpret_cast<float4*>(copy_dst), c);
        }

        // u = s_w(x), v = d_w(x) for this row
        float4 u, v;
        u.x = fmaf(2.f, c.x, xl  + c.y);
        u.y = fmaf(2.f, c.y, c.x + c.z);
        u.z = fmaf(2.f, c.z, c.y + c.w);
        u.w = fmaf(2.f, c.w, c.z + xr);
        v.x = c.y - xl;
        v.y = c.z - c.x;
        v.z = c.w - c.y;
        v.w = xr  - c.z;

        // h-combine weights: A += sh[r]*u, B += sh[r]*v, C += dh[r]*u
        const float sh = (r == 1) ? 2.f : 1.f;
        const float dh = (r == 0) ? -1.f : (r == 2 ? 1.f : 0.f);
        if (r == 1) {
            A.x = fmaf(2.f, u.x, A.x); A.y = fmaf(2.f, u.y, A.y);
            A.z = fmaf(2.f, u.z, A.z); A.w = fmaf(2.f, u.w, A.w);
            B.x = fmaf(2.f, v.x, B.x); B.y = fmaf(2.f, v.y, B.y);
            B.z = fmaf(2.f, v.z, B.z); B.w = fmaf(2.f, v.w, B.w);
        } else {
            A.x += u.x; A.y += u.y; A.z += u.z; A.w += u.w;
            B.x += v.x; B.y += v.y; B.z += v.z; B.w += v.w;
            C.x = fmaf(dh, u.x, C.x); C.y = fmaf(dh, u.y, C.y);
            C.z = fmaf(dh, u.z, C.z); C.w = fmaf(dh, u.w, C.w);
        }
        (void)sh;
    }
}

__global__ void __launch_bounds__(128, 9)
sobel_edge_kernel(const float* __restrict__ img, float* __restrict__ out)
{
    const int tx = threadIdx.x;            // 0..63 -> w (float4)
    const int ty = threadIdx.y;            // 0..1  -> h row
    const int w0 = tx * 4;
    const int h  = blockIdx.x * 2 + ty;    // h fastest: halo rows shared in L2
    const int d0 = blockIdx.y * DCHUNK;
    const int b  = blockIdx.z;

    const bool v0 = h > 0, v2 = h < DIM_H - 1;
    const bool wl = w0 > 0, wr = (w0 + 4) < DIM_W;

    const float* rp = img + (size_t)b * (DIM_D * PLANE)
                    + (size_t)(d0 - 1) * PLANE + (size_t)h * DIM_W + w0;

    // o0 tracks the copy channel at the plane currently being LOADED;
    // o1 tracks the magnitude channel at the plane currently being OUTPUT.
    float* o0 = out + (size_t)b * 2 * (DIM_D * PLANE)
              + (size_t)d0 * PLANE + (size_t)h * DIM_W + w0;
    float* o1 = o0 + (size_t)(DIM_D * PLANE);

    float4 A0, B0, C0, A1, B1, C1, A2, B2, C2;

    // Prologue: plane d0-1 (no copy store: previous chunk owns it),
    //           plane d0  (store its copy now)
    load_fold(rp, nullptr, d0 > 0, v0, v2, wl, wr, A1, B1, C1);
    rp += PLANE;
    load_fold(rp, o0, true, v0, v2, wl, wr, A2, B2, C2);
    rp += PLANE;
    o0 += PLANE;

#pragma unroll 1
    for (int dd = 0; dd < DCHUNK; dd++) {
        // rotate ring
        A0 = A1; B0 = B1; C0 = C1;
        A1 = A2; B1 = B2; C1 = C2;

        // load plane d0+dd+1; store its copy channel unless it belongs to the
        // next chunk (p == d0+DCHUNK) or is out of range
        const int p = d0 + dd + 1;
        const bool pv = p < DIM_D;
        float* cdst = (dd < DCHUNK - 1) ? o0 : nullptr;
        load_fold(rp, pv ? cdst : nullptr, pv, v0, v2, wl, wr, A2, B2, C2);
        rp += PLANE;
        o0 += PLANE;

        // magnitude for plane d0+dd
        float4 gx, gy, gz, m;
        gx.x = fmaf(2.f, B1.x, B0.x + B2.x);
        gx.y = fmaf(2.f, B1.y, B0.y + B2.y);
        gx.z = fmaf(2.f, B1.z, B0.z + B2.z);
        gx.w = fmaf(2.f, B1.w, B0.w + B2.w);
        gy.x = fmaf(2.f, C1.x, C0.x + C2.x);
        gy.y = fmaf(2.f, C1.y, C0.y + C2.y);
        gy.z = fmaf(2.f, C1.z, C0.z + C2.z);
        gy.w = fmaf(2.f, C1.w, C0.w + C2.w);
        gz.x = A2.x - A0.x;
        gz.y = A2.y - A0.y;
        gz.z = A2.z - A0.z;
        gz.w = A2.w - A0.w;
        m.x = sqrtf(fmaf(gx.x, gx.x, fmaf(gy.x, gy.x, fmaf(gz.x, gz.x, 1e-8f))));
        m.y = sqrtf(fmaf(gx.y, gx.y, fmaf(gy.y, gy.y, fmaf(gz.y, gz.y, 1e-8f))));
        m.z = sqrtf(fmaf(gx.z, gx.z, fmaf(gy.z, gy.z, fmaf(gz.z, gz.z, 1e-8f))));
        m.w = sqrtf(fmaf(gx.w, gx.w, fmaf(gy.w, gy.w, fmaf(gz.w, gz.w, 1e-8f))));

        __stcs(reinterpret_cast<float4*>(o1), m);
        o1 += PLANE;
    }
}

extern "C" void kernel_launch(void* const* d_in, const int* in_sizes, int n_in,
                              void* d_out, int out_size)
{
    const float* img = (const float*)d_in[0];
    float* out = (float*)d_out;

    dim3 block(64, 2, 1);                        // 128 threads
    dim3 grid(DIM_H / 2, DIM_D / DCHUNK, 4);     // 128 x 4 x 4 = 2048 CTAs

    sobel_edge_kernel<<<grid, block>>>(img, out);
}

// round 7
// speedup vs baseline: 2.1672x; 1.3292x over previous
#include <cuda_runtime.h>
#include <cstdint>

// image [B=4, C=1, D=128, H=256, W=256] fp32
// out   [B, 2, D, H, W]: ch0 = copy, ch1 = sqrt(Gx^2+Gy^2+Gz^2 + 1e-8)
#define DIM_D 128
#define DIM_H 256
#define DIM_W 256
#define PLANE (DIM_H * DIM_W)
#define DCHUNK 32
#define NROWS 6                     // rows h0-1 .. h0+4 staged per plane
#define STAGE_F (NROWS * DIM_W)     // 1536 floats = 6 KB per buffer

__device__ __forceinline__ void cp16(uint32_t saddr, const float* gp) {
    asm volatile("cp.async.ca.shared.global [%0], [%1], 16;" :: "r"(saddr), "l"(gp));
}
__device__ __forceinline__ void cp_commit() { asm volatile("cp.async.commit_group;"); }
__device__ __forceinline__ void cp_wait1()  { asm volatile("cp.async.wait_group 1;" ::: "memory"); }
__device__ __forceinline__ void cp_wait2()  { asm volatile("cp.async.wait_group 2;" ::: "memory"); }

// Fold one staged plane (smem) into separable partials for this thread's row:
//   A = s_h*s_w(x) (Gz=d_d(A)); B = s_h*d_w(x) (Gx=s_d(B)); C = d_h*s_w(x) (Gy=s_d(C))
__device__ __forceinline__ void fold_smem(
    const float* __restrict__ sB,   // &sbuf[s][ty*DIM_W + w0]
    bool wl, bool wr,
    float4& A, float4& B, float4& C, float4* cen)
{
    A = make_float4(0.f, 0.f, 0.f, 0.f);
    B = A; C = A;
#pragma unroll
    for (int r = 0; r < 3; r++) {
        const float* row = sB + r * DIM_W;
        const float4 c = *reinterpret_cast<const float4*>(row);
        const float xl = wl ? row[-1] : 0.f;
        const float xr = wr ? row[4]  : 0.f;
        if (r == 1 && cen) *cen = c;

        float4 u, v;
        u.x = fmaf(2.f, c.x, xl  + c.y);
        u.y = fmaf(2.f, c.y, c.x + c.z);
        u.z = fmaf(2.f, c.z, c.y + c.w);
        u.w = fmaf(2.f, c.w, c.z + xr);
        v.x = c.y - xl;
        v.y = c.z - c.x;
        v.z = c.w - c.y;
        v.w = xr  - c.z;

        if (r == 1) {
            A.x = fmaf(2.f, u.x, A.x); A.y = fmaf(2.f, u.y, A.y);
            A.z = fmaf(2.f, u.z, A.z); A.w = fmaf(2.f, u.w, A.w);
            B.x = fmaf(2.f, v.x, B.x); B.y = fmaf(2.f, v.y, B.y);
            B.z = fmaf(2.f, v.z, B.z); B.w = fmaf(2.f, v.w, B.w);
        } else {
            const float dh = (r == 0) ? -1.f : 1.f;
            A.x += u.x; A.y += u.y; A.z += u.z; A.w += u.w;
            B.x += v.x; B.y += v.y; B.z += v.z; B.w += v.w;
            C.x = fmaf(dh, u.x, C.x); C.y = fmaf(dh, u.y, C.y);
            C.z = fmaf(dh, u.z, C.z); C.w = fmaf(dh, u.w, C.w);
        }
    }
}

__global__ void __launch_bounds__(256, 4)
sobel_edge_kernel(const float* __restrict__ img, float* __restrict__ out)
{
    __shared__ float sbuf[3][STAGE_F];

    const int tx  = threadIdx.x;           // 0..63 -> w (float4)
    const int ty  = threadIdx.y;           // 0..3  -> h row
    const int tid = tx + ty * 64;          // 0..255
    const int w0  = tx * 4;
    const int h0  = blockIdx.x * 4;
    const int h   = h0 + ty;
    const int d0  = blockIdx.y * DCHUNK;
    const int b   = blockIdx.z;

    const bool wl = w0 > 0, wr = (w0 + 4) < DIM_W;

    const float* gbase = img + (size_t)b * (DIM_D * PLANE);

    // --- staging assignment: 384 16B chunks (6 rows x 64 float4) per plane ---
    // element 0: idx = tid (0..255); element 1: idx = tid+256 (valid < 384)
    const int r0 = tid >> 6,          c0 = tid & 63;
    const int r1 = (tid + 256) >> 6,  c1 = (tid + 256) & 63;
    const bool has1 = (tid + 256) < NROWS * 64;
    const int g0 = h0 - 1 + r0;
    const int g1 = h0 - 1 + r1;
    const bool gv0 = (g0 >= 0) && (g0 < DIM_H);
    const bool gv1 = (g1 >= 0) && (g1 < DIM_H);
    const float* gr0 = gbase + (size_t)g0 * DIM_W + c0 * 4;   // + p*PLANE at use
    const float* gr1 = gbase + (size_t)g1 * DIM_W + c1 * 4;
    const uint32_t sB0 = (uint32_t)__cvta_generic_to_shared(&sbuf[0][0]);
    const uint32_t so0 = (uint32_t)(r0 * DIM_W + c0 * 4) * 4u;
    const uint32_t so1 = (uint32_t)(r1 * DIM_W + c1 * 4) * 4u;
    float* z0 = &sbuf[0][r0 * DIM_W + c0 * 4];  // generic ptrs for zero-fill
    float* z1 = &sbuf[0][r1 * DIM_W + c1 * 4];

    const float4 f4z = make_float4(0.f, 0.f, 0.f, 0.f);

    // Stage plane p into buffer s (zero-fills invalid plane/rows). Always commits.
    auto stage = [&](int s, int p, bool need) {
        if (need) {
            const bool pv = (p >= 0) && (p < DIM_D);
            const size_t poff = (size_t)p * PLANE;
            const uint32_t sbase = sB0 + (uint32_t)s * (STAGE_F * 4u);
            if (pv && gv0) cp16(sbase + so0, gr0 + poff);
            else *reinterpret_cast<float4*>(z0 + s * STAGE_F) = f4z;
            if (has1) {
                if (pv && gv1) cp16(sbase + so1, gr1 + poff);
                else *reinterpret_cast<float4*>(z1 + s * STAGE_F) = f4z;
            }
        }
        cp_commit();
    };

    // Output pointers
    float* o0 = out + (size_t)b * 2 * (DIM_D * PLANE)
              + (size_t)d0 * PLANE + (size_t)h * DIM_W + w0;   // copy ch, plane d0
    float* o1 = o0 + (size_t)(DIM_D * PLANE);                  // mag ch, plane d0
    const float* sMy = &sbuf[0][ty * DIM_W + w0];              // my fold window in buf0

    float4 A0, B0, C0, A1, B1, C1, A2, B2, C2, cen;

    // --- prologue: stage planes d0-1, d0, d0+1 into bufs 0,1,2 ---
    stage(0, d0 - 1, true);
    stage(1, d0,     true);
    stage(2, d0 + 1, true);
    cp_wait2();
    __syncthreads();
    fold_smem(sMy, wl, wr, A1, B1, C1, nullptr);                  // plane d0-1
    cp_wait1();
    __syncthreads();
    fold_smem(sMy + STAGE_F, wl, wr, A2, B2, C2, &cen);           // plane d0
    __stcs(reinterpret_cast<float4*>(o0), cen);                   // copy(d0)
    o0 += PLANE;                                                  // -> plane d0+1

    int sw = 0;   // write buffer for this iter
    int sr = 2;   // read (fold) buffer for this iter

#pragma unroll 1
    for (int dd = 0; dd < DCHUNK; dd++) {
        // (1) stage plane d0+dd+2 into buf sw (not needed on last iter)
        stage(sw, d0 + dd + 2, dd < DCHUNK - 1);

        // (2) wait for plane d0+dd+1 (committed 2 groups ago), sync, fold it
        cp_wait1();
        __syncthreads();
        A0 = A1; B0 = B1; C0 = C1;
        A1 = A2; B1 = B2; C1 = C2;
        fold_smem(&sbuf[sr][ty * DIM_W + w0], wl, wr, A2, B2, C2, &cen);
        if (dd < DCHUNK - 1) {                    // copy(d0+dd+1) owned by this chunk
            __stcs(reinterpret_cast<float4*>(o0), cen);
        }
        o0 += PLANE;

        // (3) magnitude for plane d0+dd
        float4 gx, gy, gz, m;
        gx.x = fmaf(2.f, B1.x, B0.x + B2.x);
        gx.y = fmaf(2.f, B1.y, B0.y + B2.y);
        gx.z = fmaf(2.f, B1.z, B0.z + B2.z);
        gx.w = fmaf(2.f, B1.w, B0.w + B2.w);
        gy.x = fmaf(2.f, C1.x, C0.x + C2.x);
        gy.y = fmaf(2.f, C1.y, C0.y + C2.y);
        gy.z = fmaf(2.f, C1.z, C0.z + C2.z);
        gy.w = fmaf(2.f, C1.w, C0.w + C2.w);
        gz.x = A2.x - A0.x;
        gz.y = A2.y - A0.y;
        gz.z = A2.z - A0.z;
        gz.w = A2.w - A0.w;
        m.x = sqrtf(fmaf(gx.x, gx.x, fmaf(gy.x, gy.x, fmaf(gz.x, gz.x, 1e-8f))));
        m.y = sqrtf(fmaf(gx.y, gx.y, fmaf(gy.y, gy.y, fmaf(gz.y, gz.y, 1e-8f))));
        m.z = sqrtf(fmaf(gx.z, gx.z, fmaf(gy.z, gy.z, fmaf(gz.z, gz.z, 1e-8f))));
        m.w = sqrtf(fmaf(gx.w, gx.w, fmaf(gy.w, gy.w, fmaf(gz.w, gz.w, 1e-8f))));

        __stcs(reinterpret_cast<float4*>(o1), m);
        o1 += PLANE;

        // advance buffer ring
        sw = (sw == 2) ? 0 : sw + 1;
        sr = (sr == 2) ? 0 : sr + 1;
    }
}

extern "C" void kernel_launch(void* const* d_in, const int* in_sizes, int n_in,
                              void* d_out, int out_size)
{
    const float* img = (const float*)d_in[0];
    float* out = (float*)d_out;

    dim3 block(64, 4, 1);                        // 256 threads
    dim3 grid(DIM_H / 4, DIM_D / DCHUNK, 4);     // 64 x 4 x 4 = 1024 CTAs

    sobel_edge_kernel<<<grid, block>>>(img, out);
}